// round 15
// baseline (speedup 1.0000x reference)
#include <cuda_runtime.h>

#define NN       50000
#define HC       128
#define NEG      0.2f
#define SCAP     256
#define MAXTGT   1024
#define LCAP     32768
#define BMWORDS  ((NN + 31) / 32)
#define STB      64                // stats blocks

// ---------------- device scratch (zero-initialized at load) ----------------
__device__ unsigned g_bitmap[BMWORDS];
__device__ int      g_nodelist[SCAP];
__device__ int      g_tgt_src[MAXTGT];
__device__ float    g_tgt_a[MAXTGT];
__device__ int      g_Lslot[LCAP];
__device__ float    g_Lxs[LCAP];
__device__ float    g_La[LCAP];
__device__ float    g_ssum[4 * SCAP];
__device__ float    g_xl2[SCAP * HC];
__device__ float    g_xr2t[HC];
__device__ int      g_tcount, g_nnodes, g_lcount;
__device__ double   g_easum;
__device__ float    g_fill;
__device__ int      g_flag;        // 0 = scratch dirty; 1 = cleared (set by scan1 blk0)

__device__ __forceinline__ float lrelu(float v) { return v > 0.f ? v : NEG * v; }

// ---------------- K1: inline clear (block 0) + scan dst: target in-edges + flags ----
__global__ void k_scan1(const int* __restrict__ src, const int* __restrict__ dst,
                        const float* __restrict__ ea, const int* tgtp, int E) {
    int tid = threadIdx.x;
    if (blockIdx.x == 0) {
        // clear all per-call scratch, then publish
        int tgt = *tgtp;
        int tw = tgt >> 5;
        for (int j = tid; j < BMWORDS; j += blockDim.x)
            g_bitmap[j] = (j == tw) ? (1u << (tgt & 31)) : 0u;
        for (int j = tid; j < 4 * SCAP; j += blockDim.x) g_ssum[j] = 0.f;
        if (tid == 0) {
            g_tcount = 0; g_nnodes = 1; g_lcount = 0; g_easum = 0.0;
            g_nodelist[0] = tgt;
        }
        __syncthreads();
        if (tid == 0) {
            __threadfence();
            *((volatile int*)&g_flag) = 1;
        }
        __syncthreads();
    } else {
        if (tid == 0) {
            volatile int* vf = &g_flag;
            while (*vf == 0) { }
            __threadfence();
        }
        __syncthreads();
    }

    int tgt = *tgtp;
    int i = blockIdx.x * blockDim.x + tid;
    int stride = gridDim.x * blockDim.x;
    int nv = E >> 2;
    const int4* d4 = (const int4*)dst;
    for (int v = i; v < nv; v += stride) {
        int4 d = d4[v];
        int e = v << 2;
        #pragma unroll
        for (int c = 0; c < 4; c++) {
            int dd = (c == 0) ? d.x : (c == 1) ? d.y : (c == 2) ? d.z : d.w;
            if (dd == tgt) {
                int idx = atomicAdd(&g_tcount, 1);
                int s = src[e + c];
                if (idx < MAXTGT) { g_tgt_src[idx] = s; g_tgt_a[idx] = ea[e + c]; }
                unsigned m = 1u << (s & 31);
                unsigned old = atomicOr(&g_bitmap[s >> 5], m);
                if (!(old & m)) {
                    int sl = atomicAdd(&g_nnodes, 1);
                    if (sl < SCAP) g_nodelist[sl] = s;
                }
            }
        }
    }
    for (int e = (nv << 2) + i; e < E; e += stride) {
        if (dst[e] == tgt) {
            int idx = atomicAdd(&g_tcount, 1);
            int s = src[e];
            if (idx < MAXTGT) { g_tgt_src[idx] = s; g_tgt_a[idx] = ea[e]; }
            unsigned m = 1u << (s & 31);
            unsigned old = atomicOr(&g_bitmap[s >> 5], m);
            if (!(old & m)) {
                int sl = atomicAdd(&g_nnodes, 1);
                if (sl < SCAP) g_nodelist[sl] = s;
            }
        }
    }
}

// ---------------- K2: collect edges into flagged nodes + ea sum ----------------
__global__ void k_scan2(const int* __restrict__ src, const int* __restrict__ dst,
                        const float* __restrict__ ea, const float* __restrict__ x, int E) {
    __shared__ unsigned sbm[BMWORDS];
    __shared__ int snl[SCAP];
    __shared__ int snn;
    int tid = threadIdx.x;
    int i = blockIdx.x * blockDim.x + tid;
    int stride = gridDim.x * blockDim.x;

    for (int j = tid; j < BMWORDS; j += blockDim.x) sbm[j] = g_bitmap[j];
    if (tid == 0) snn = min(g_nnodes, SCAP);
    __syncthreads();
    int nn = snn;
    for (int j = tid; j < nn; j += blockDim.x) snl[j] = g_nodelist[j];
    __syncthreads();

    int nv = E >> 2;
    const int4* d4 = (const int4*)dst;
    const float4* a4 = (const float4*)ea;
    float ax = 0.f, ay = 0.f, az = 0.f, aw = 0.f;
    for (int v = i; v < nv; v += stride) {
        int4 d = d4[v];
        float4 a = a4[v];
        ax += a.x; ay += a.y; az += a.z; aw += a.w;
        int e = v << 2;
        #pragma unroll
        for (int c = 0; c < 4; c++) {
            int dd = (c == 0) ? d.x : (c == 1) ? d.y : (c == 2) ? d.z : d.w;
            if ((sbm[dd >> 5] >> (dd & 31)) & 1u) {
                float aa = (c == 0) ? a.x : (c == 1) ? a.y : (c == 2) ? a.z : a.w;
                int slot = 0;
                for (int t = 0; t < nn; t++) { if (snl[t] == dd) { slot = t; break; } }
                int idx = atomicAdd(&g_lcount, 1);
                if (idx < LCAP) {
                    g_Lslot[idx] = slot;
                    g_Lxs[idx]   = x[src[e + c]];
                    g_La[idx]    = aa;
                }
            }
        }
    }
    for (int e = (nv << 2) + i; e < E; e += stride) {
        int dd = dst[e];
        ax += ea[e];
        if ((sbm[dd >> 5] >> (dd & 31)) & 1u) {
            int slot = 0;
            for (int t = 0; t < nn; t++) { if (snl[t] == dd) { slot = t; break; } }
            int idx = atomicAdd(&g_lcount, 1);
            if (idx < LCAP) {
                g_Lslot[idx] = slot; g_Lxs[idx] = x[src[e]]; g_La[idx] = ea[e];
            }
        }
    }
    __shared__ double sd[256];
    sd[tid] = (double)((ax + ay) + (az + aw)); __syncthreads();
    for (int off = blockDim.x >> 1; off; off >>= 1) {
        if (tid < off) sd[tid] += sd[tid + off];
        __syncthreads();
    }
    if (tid == 0) atomicAdd(&g_easum, sd[0]);
}

// ---------------- K3: conv1 stats — multi-block, global atomic sums ----------------
__global__ void __launch_bounds__(256) k_stats(
        const float* __restrict__ x,
        const float* __restrict__ Wl1, const float* __restrict__ bl1,
        const float* __restrict__ Wr1, const float* __restrict__ br1,
        const float* __restrict__ We1, const float* __restrict__ att1, int E) {
    int tid = threadIdx.x, bid = blockIdx.x;
    int nn = min(g_nnodes, SCAP);
    int lc = min(g_lcount, LCAP);
    int total = lc + nn;
    float fill = (float)(g_easum / (double)E);
    if (bid == 0 && tid == 0) g_fill = fill;

    __shared__ float sWl1[HC], sWr1[HC], sWe1[HC], sAtt1[HC], sBlr[HC];
    __shared__ float sxd[SCAP];
    if (tid < HC) {
        sWl1[tid] = Wl1[tid]; sWr1[tid] = Wr1[tid]; sWe1[tid] = We1[tid];
        sAtt1[tid] = att1[tid];
        sBlr[tid] = bl1[tid] + br1[tid];
    }
    for (int j = tid; j < nn; j += 256) sxd[j] = x[g_nodelist[j]];
    __syncthreads();

    for (int i = bid + STB * tid; i < total; i += STB * 256) {
        int slot; float xs, a;
        if (i < lc) { slot = g_Lslot[i]; xs = g_Lxs[i]; a = g_La[i]; }
        else        { slot = i - lc;     xs = sxd[slot]; a = fill; }
        float xd = sxd[slot];
        float p0 = 0.f, p1 = 0.f;
        #pragma unroll 8
        for (int j = 0; j < HC; j++) {
            float v = fmaf(xs, sWl1[j], fmaf(a, sWe1[j], fmaf(xd, sWr1[j], sBlr[j])));
            v = lrelu(v);
            float p = v * sAtt1[j];
            if (j < 64) p0 += p; else p1 += p;
        }
        float e0 = expf(p0), e1 = expf(p1);     // logits bounded; no max needed
        atomicAdd(&g_ssum[4 * slot],     e0);
        atomicAdd(&g_ssum[4 * slot + 1], e1);
        atomicAdd(&g_ssum[4 * slot + 2], e0 * xs);
        atomicAdd(&g_ssum[4 * slot + 3], e1 * xs);
    }
}

// ---------------- K4: parallel GEMM — h1 in-block; xl2 per slot + xr2t (block 63) ----
__global__ void __launch_bounds__(512) k_gemm(
        const float* __restrict__ Wl1, const float* __restrict__ bl1,
        const float* __restrict__ b1,
        const float* __restrict__ Wl2, const float* __restrict__ bl2,
        const float* __restrict__ Wr2, const float* __restrict__ br2) {
    int tid = threadIdx.x, c = tid & 127, q = tid >> 7;
    int nn = min(g_nnodes, SCAP);
    __shared__ float sh[HC];
    __shared__ float sred[3][HC];

    if (blockIdx.x < 63) {
        for (int s = blockIdx.x; s < nn; s += 63) {
            if (tid < HC) {
                float S = (tid < 64) ? g_ssum[4 * s + 2] / g_ssum[4 * s]
                                     : g_ssum[4 * s + 3] / g_ssum[4 * s + 1];
                sh[tid] = fmaxf(fmaf(Wl1[tid], S, bl1[tid] + b1[tid]), 0.f);
            }
            __syncthreads();
            float acc = 0.f;
            const float* W = Wl2 + (q * 32) * HC + c;
            #pragma unroll
            for (int k = 0; k < 32; k++)
                acc = fmaf(sh[q * 32 + k], W[k * HC], acc);
            if (q > 0) sred[q - 1][c] = acc;
            __syncthreads();
            if (q == 0)
                g_xl2[s * HC + c] = acc + sred[0][c] + sred[1][c] + sred[2][c] + bl2[c];
            __syncthreads();
        }
    } else {
        if (tid < HC) {            // slot 0 == target
            float S = (tid < 64) ? g_ssum[2] / g_ssum[0] : g_ssum[3] / g_ssum[1];
            sh[tid] = fmaxf(fmaf(Wl1[tid], S, bl1[tid] + b1[tid]), 0.f);
        }
        __syncthreads();
        float acc = 0.f;
        const float* W = Wr2 + (q * 32) * HC + c;
        #pragma unroll
        for (int k = 0; k < 32; k++)
            acc = fmaf(sh[q * 32 + k], W[k * HC], acc);
        if (q > 0) sred[q - 1][c] = acc;
        __syncthreads();
        if (q == 0)
            g_xr2t[c] = acc + sred[0][c] + sred[1][c] + sred[2][c] + br2[c];
    }
}

// ---------------- K5: conv2 at target + fc (no-max softmax) + flag clear ----------------
__global__ void __launch_bounds__(512) k_final(
        const float* __restrict__ We2, const float* __restrict__ att2,
        const float* __restrict__ b2,
        const float* __restrict__ Wfc, const float* __restrict__ bfc,
        float* __restrict__ out) {
    int tid = threadIdx.x, lane = tid & 31, w = tid >> 5;
    int c = tid & 127, q = tid >> 7;
    int nn = min(g_nnodes, SCAP);
    int tc = min(g_tcount, MAXTGT);
    int items = tc + 1;
    float fill = g_fill;

    if (tid == 0) *((volatile int*)&g_flag) = 0;   // re-arm scan1's clear for next call

    __shared__ float sxr[HC], sO[HC];
    __shared__ float sred2[3][HC];
    __shared__ int   snl[SCAP];
    __shared__ float sal0[MAXTGT + 1], sal1[MAXTGT + 1];
    __shared__ int   sslot[MAXTGT + 1];
    __shared__ float tsum0, tsum1;

    if (tid < HC) sxr[tid] = g_xr2t[tid];
    for (int j = tid; j < nn; j += 512) snl[j] = g_nodelist[j];
    if (tid == 0) { tsum0 = 0.f; tsum1 = 0.f; }
    __syncthreads();

    for (int i = w; i < items; i += 16) {
        int slot = 0; float a;
        if (i < tc) {
            int sn = g_tgt_src[i];
            for (int t = 0; t < nn; t++) { if (snl[t] == sn) { slot = t; break; } }
            a = g_tgt_a[i];
        } else { slot = 0; a = fill; }
        float p0 = 0.f, p1 = 0.f;
        #pragma unroll
        for (int k = 0; k < 4; k++) {
            int cc = lane + 32 * k;
            float vv = g_xl2[slot * HC + cc] + sxr[cc] + a * We2[cc];
            vv = lrelu(vv);
            float p = vv * att2[cc];
            if (k < 2) p0 += p; else p1 += p;
        }
        #pragma unroll
        for (int off = 16; off; off >>= 1) {
            p0 += __shfl_down_sync(0xffffffffu, p0, off);
            p1 += __shfl_down_sync(0xffffffffu, p1, off);
        }
        if (lane == 0) {
            float e0 = expf(p0), e1 = expf(p1);
            sal0[i] = e0; sal1[i] = e1;
            sslot[i] = slot;
            atomicAdd(&tsum0, e0); atomicAdd(&tsum1, e1);
        }
    }
    __syncthreads();

    float inv = (c < 64) ? (1.f / tsum0) : (1.f / tsum1);
    float agg = 0.f;
    for (int i = q; i < items; i += 4) {
        float al = ((c < 64) ? sal0[i] : sal1[i]) * inv;
        agg = fmaf(al, g_xl2[sslot[i] * HC + c], agg);
    }
    if (q > 0) sred2[q - 1][c] = agg;
    __syncthreads();
    if (q == 0) sO[c] = agg + sred2[0][c] + sred2[1][c] + sred2[2][c] + b2[c];
    __syncthreads();

    float r = 0.f;
    const float* Wf = Wfc + (q * 32) * HC + c;
    #pragma unroll
    for (int k = 0; k < 32; k++)
        r = fmaf(sO[q * 32 + k], Wf[k * HC], r);
    if (q > 0) sred2[q - 1][c] = r;
    __syncthreads();
    if (q == 0) out[c] = r + sred2[0][c] + sred2[1][c] + sred2[2][c] + bfc[c];
}

// ---------------- launch ----------------
extern "C" void kernel_launch(void* const* d_in, const int* in_sizes, int n_in,
                              void* d_out, int out_size) {
    const float* x    = (const float*)d_in[0];
    const int*   ei   = (const int*)  d_in[1];
    const float* ea   = (const float*)d_in[2];
    const int*   tgtp = (const int*)  d_in[3];
    const float* Wl1  = (const float*)d_in[4];
    const float* bl1  = (const float*)d_in[5];
    const float* Wr1  = (const float*)d_in[6];
    const float* br1  = (const float*)d_in[7];
    const float* We1  = (const float*)d_in[8];
    const float* att1 = (const float*)d_in[9];
    const float* b1   = (const float*)d_in[10];
    const float* Wl2  = (const float*)d_in[11];
    const float* bl2  = (const float*)d_in[12];
    const float* Wr2  = (const float*)d_in[13];
    const float* br2  = (const float*)d_in[14];
    const float* We2  = (const float*)d_in[15];
    const float* att2 = (const float*)d_in[16];
    const float* b2   = (const float*)d_in[17];
    const float* Wfc  = (const float*)d_in[18];
    const float* bfc  = (const float*)d_in[19];
    float* out = (float*)d_out;

    int E = in_sizes[1] / 2;
    const int* src = ei;
    const int* dst = ei + E;

    k_scan1<<<592, 256>>>(src, dst, ea, tgtp, E);
    k_scan2<<<592, 256>>>(src, dst, ea, x, E);
    k_stats<<<STB, 256>>>(x, Wl1, bl1, Wr1, br1, We1, att1, E);
    k_gemm <<<64, 512>>>(Wl1, bl1, b1, Wl2, bl2, Wr2, br2);
    k_final<<<1, 512>>>(We2, att2, b2, Wfc, bfc, out);
    (void)n_in; (void)out_size;
}

// round 16
// speedup vs baseline: 1.0667x; 1.0667x over previous
#include <cuda_runtime.h>

#define NN       50000
#define HC       128
#define NEG      0.2f
#define SCAP     256
#define MAXTGT   1024
#define LCAP     32768
#define BMWORDS  ((NN + 31) / 32)
#define STB      64                // stats blocks

// ---------------- device scratch ----------------
__device__ unsigned g_bitmap[BMWORDS];
__device__ int      g_nodelist[SCAP];
__device__ int      g_tgt_src[MAXTGT];
__device__ float    g_tgt_a[MAXTGT];
__device__ int      g_Lslot[LCAP];
__device__ float    g_Lxs[LCAP];
__device__ float    g_La[LCAP];
__device__ float    g_ssum[4 * SCAP];
__device__ float    g_xl2[SCAP * HC];
__device__ float    g_xr2t[HC];
__device__ int      g_tcount, g_nnodes, g_lcount;
__device__ double   g_easum;
__device__ float    g_fill;

__device__ __forceinline__ float lrelu(float v) { return v > 0.f ? v : NEG * v; }

// ---------------- K0: reset (lean — steady-state L2 already holds weights/x) ----------------
__global__ void k_reset(const int* tgtp) {
    int tgt = *tgtp;
    int i = blockIdx.x * blockDim.x + threadIdx.x;
    int stride = gridDim.x * blockDim.x;
    int tw = tgt >> 5;
    for (int j = i; j < BMWORDS; j += stride)
        g_bitmap[j] = (j == tw) ? (1u << (tgt & 31)) : 0u;
    for (int j = i; j < 4 * SCAP; j += stride) g_ssum[j] = 0.f;
    if (i == 0) {
        g_tcount = 0; g_nnodes = 1; g_lcount = 0; g_easum = 0.0;
        g_nodelist[0] = tgt;
    }
}

// ---------------- K1: scan dst only: target in-edges + flag sources ----------------
__global__ void k_scan1(const int* __restrict__ src, const int* __restrict__ dst,
                        const float* __restrict__ ea, const int* tgtp, int E) {
    int tgt = *tgtp;
    int i = blockIdx.x * blockDim.x + threadIdx.x;
    int stride = gridDim.x * blockDim.x;
    int nv = E >> 2;
    const int4* d4 = (const int4*)dst;
    for (int v = i; v < nv; v += stride) {
        int4 d = d4[v];
        int e = v << 2;
        #pragma unroll
        for (int c = 0; c < 4; c++) {
            int dd = (c == 0) ? d.x : (c == 1) ? d.y : (c == 2) ? d.z : d.w;
            if (dd == tgt) {
                int idx = atomicAdd(&g_tcount, 1);
                int s = src[e + c];
                if (idx < MAXTGT) { g_tgt_src[idx] = s; g_tgt_a[idx] = ea[e + c]; }
                unsigned m = 1u << (s & 31);
                unsigned old = atomicOr(&g_bitmap[s >> 5], m);
                if (!(old & m)) {
                    int sl = atomicAdd(&g_nnodes, 1);
                    if (sl < SCAP) g_nodelist[sl] = s;
                }
            }
        }
    }
    for (int e = (nv << 2) + i; e < E; e += stride) {
        if (dst[e] == tgt) {
            int idx = atomicAdd(&g_tcount, 1);
            int s = src[e];
            if (idx < MAXTGT) { g_tgt_src[idx] = s; g_tgt_a[idx] = ea[e]; }
            unsigned m = 1u << (s & 31);
            unsigned old = atomicOr(&g_bitmap[s >> 5], m);
            if (!(old & m)) {
                int sl = atomicAdd(&g_nnodes, 1);
                if (sl < SCAP) g_nodelist[sl] = s;
            }
        }
    }
}

// ---------------- K2: collect edges into flagged nodes + ea sum ----------------
__global__ void k_scan2(const int* __restrict__ src, const int* __restrict__ dst,
                        const float* __restrict__ ea, const float* __restrict__ x, int E) {
    __shared__ unsigned sbm[BMWORDS];
    __shared__ int snl[SCAP];
    __shared__ int snn;
    int tid = threadIdx.x;
    int i = blockIdx.x * blockDim.x + tid;
    int stride = gridDim.x * blockDim.x;

    for (int j = tid; j < BMWORDS; j += blockDim.x) sbm[j] = g_bitmap[j];
    if (tid == 0) snn = min(g_nnodes, SCAP);
    __syncthreads();
    int nn = snn;
    for (int j = tid; j < nn; j += blockDim.x) snl[j] = g_nodelist[j];
    __syncthreads();

    int nv = E >> 2;
    const int4* d4 = (const int4*)dst;
    const float4* a4 = (const float4*)ea;
    float ax = 0.f, ay = 0.f, az = 0.f, aw = 0.f;
    for (int v = i; v < nv; v += stride) {
        int4 d = d4[v];
        float4 a = a4[v];
        ax += a.x; ay += a.y; az += a.z; aw += a.w;
        int e = v << 2;
        #pragma unroll
        for (int c = 0; c < 4; c++) {
            int dd = (c == 0) ? d.x : (c == 1) ? d.y : (c == 2) ? d.z : d.w;
            if ((sbm[dd >> 5] >> (dd & 31)) & 1u) {
                float aa = (c == 0) ? a.x : (c == 1) ? a.y : (c == 2) ? a.z : a.w;
                int slot = 0;
                for (int t = 0; t < nn; t++) { if (snl[t] == dd) { slot = t; break; } }
                int idx = atomicAdd(&g_lcount, 1);
                if (idx < LCAP) {
                    g_Lslot[idx] = slot;
                    g_Lxs[idx]   = x[src[e + c]];
                    g_La[idx]    = aa;
                }
            }
        }
    }
    for (int e = (nv << 2) + i; e < E; e += stride) {
        int dd = dst[e];
        ax += ea[e];
        if ((sbm[dd >> 5] >> (dd & 31)) & 1u) {
            int slot = 0;
            for (int t = 0; t < nn; t++) { if (snl[t] == dd) { slot = t; break; } }
            int idx = atomicAdd(&g_lcount, 1);
            if (idx < LCAP) {
                g_Lslot[idx] = slot; g_Lxs[idx] = x[src[e]]; g_La[idx] = ea[e];
            }
        }
    }
    __shared__ double sd[256];
    sd[tid] = (double)((ax + ay) + (az + aw)); __syncthreads();
    for (int off = blockDim.x >> 1; off; off >>= 1) {
        if (tid < off) sd[tid] += sd[tid + off];
        __syncthreads();
    }
    if (tid == 0) atomicAdd(&g_easum, sd[0]);
}

// ---------------- K3: conv1 stats — multi-block, global atomic sums ----------------
__global__ void __launch_bounds__(256) k_stats(
        const float* __restrict__ x,
        const float* __restrict__ Wl1, const float* __restrict__ bl1,
        const float* __restrict__ Wr1, const float* __restrict__ br1,
        const float* __restrict__ We1, const float* __restrict__ att1, int E) {
    int tid = threadIdx.x, bid = blockIdx.x;
    int nn = min(g_nnodes, SCAP);
    int lc = min(g_lcount, LCAP);
    int total = lc + nn;
    float fill = (float)(g_easum / (double)E);
    if (bid == 0 && tid == 0) g_fill = fill;

    __shared__ float sWl1[HC], sWr1[HC], sWe1[HC], sAtt1[HC], sBlr[HC];
    __shared__ float sxd[SCAP];
    if (tid < HC) {
        sWl1[tid] = Wl1[tid]; sWr1[tid] = Wr1[tid]; sWe1[tid] = We1[tid];
        sAtt1[tid] = att1[tid];
        sBlr[tid] = bl1[tid] + br1[tid];
    }
    for (int j = tid; j < nn; j += 256) sxd[j] = x[g_nodelist[j]];
    __syncthreads();

    for (int i = bid + STB * tid; i < total; i += STB * 256) {
        int slot; float xs, a;
        if (i < lc) { slot = g_Lslot[i]; xs = g_Lxs[i]; a = g_La[i]; }
        else        { slot = i - lc;     xs = sxd[slot]; a = fill; }
        float xd = sxd[slot];
        float p0 = 0.f, p1 = 0.f;
        #pragma unroll 8
        for (int j = 0; j < HC; j++) {
            float v = fmaf(xs, sWl1[j], fmaf(a, sWe1[j], fmaf(xd, sWr1[j], sBlr[j])));
            v = lrelu(v);
            float p = v * sAtt1[j];
            if (j < 64) p0 += p; else p1 += p;
        }
        float e0 = expf(p0), e1 = expf(p1);     // logits bounded; no max needed
        atomicAdd(&g_ssum[4 * slot],     e0);
        atomicAdd(&g_ssum[4 * slot + 1], e1);
        atomicAdd(&g_ssum[4 * slot + 2], e0 * xs);
        atomicAdd(&g_ssum[4 * slot + 3], e1 * xs);
    }
}

// ---------------- K4: parallel GEMM — h1 in-block; xl2 per slot + xr2t (block 63) ----
__global__ void __launch_bounds__(512) k_gemm(
        const float* __restrict__ Wl1, const float* __restrict__ bl1,
        const float* __restrict__ b1,
        const float* __restrict__ Wl2, const float* __restrict__ bl2,
        const float* __restrict__ Wr2, const float* __restrict__ br2) {
    int tid = threadIdx.x, c = tid & 127, q = tid >> 7;
    int nn = min(g_nnodes, SCAP);
    __shared__ float sh[HC];
    __shared__ float sred[3][HC];

    if (blockIdx.x < 63) {
        for (int s = blockIdx.x; s < nn; s += 63) {
            if (tid < HC) {
                float S = (tid < 64) ? g_ssum[4 * s + 2] / g_ssum[4 * s]
                                     : g_ssum[4 * s + 3] / g_ssum[4 * s + 1];
                sh[tid] = fmaxf(fmaf(Wl1[tid], S, bl1[tid] + b1[tid]), 0.f);
            }
            __syncthreads();
            float acc = 0.f;
            const float* W = Wl2 + (q * 32) * HC + c;
            #pragma unroll
            for (int k = 0; k < 32; k++)
                acc = fmaf(sh[q * 32 + k], W[k * HC], acc);
            if (q > 0) sred[q - 1][c] = acc;
            __syncthreads();
            if (q == 0)
                g_xl2[s * HC + c] = acc + sred[0][c] + sred[1][c] + sred[2][c] + bl2[c];
            __syncthreads();
        }
    } else {
        if (tid < HC) {            // slot 0 == target
            float S = (tid < 64) ? g_ssum[2] / g_ssum[0] : g_ssum[3] / g_ssum[1];
            sh[tid] = fmaxf(fmaf(Wl1[tid], S, bl1[tid] + b1[tid]), 0.f);
        }
        __syncthreads();
        float acc = 0.f;
        const float* W = Wr2 + (q * 32) * HC + c;
        #pragma unroll
        for (int k = 0; k < 32; k++)
            acc = fmaf(sh[q * 32 + k], W[k * HC], acc);
        if (q > 0) sred[q - 1][c] = acc;
        __syncthreads();
        if (q == 0)
            g_xr2t[c] = acc + sred[0][c] + sred[1][c] + sred[2][c] + br2[c];
    }
}

// ---------------- K5: conv2 at target + fc (no-max softmax) ----------------
__global__ void __launch_bounds__(512) k_final(
        const float* __restrict__ We2, const float* __restrict__ att2,
        const float* __restrict__ b2,
        const float* __restrict__ Wfc, const float* __restrict__ bfc,
        float* __restrict__ out) {
    int tid = threadIdx.x, lane = tid & 31, w = tid >> 5;
    int c = tid & 127, q = tid >> 7;
    int nn = min(g_nnodes, SCAP);
    int tc = min(g_tcount, MAXTGT);
    int items = tc + 1;
    float fill = g_fill;

    __shared__ float sxr[HC], sO[HC];
    __shared__ float sred2[3][HC];
    __shared__ int   snl[SCAP];
    __shared__ float sal0[MAXTGT + 1], sal1[MAXTGT + 1];
    __shared__ int   sslot[MAXTGT + 1];
    __shared__ float tsum0, tsum1;

    if (tid < HC) sxr[tid] = g_xr2t[tid];
    for (int j = tid; j < nn; j += 512) snl[j] = g_nodelist[j];
    if (tid == 0) { tsum0 = 0.f; tsum1 = 0.f; }
    __syncthreads();

    for (int i = w; i < items; i += 16) {
        int slot = 0; float a;
        if (i < tc) {
            int sn = g_tgt_src[i];
            for (int t = 0; t < nn; t++) { if (snl[t] == sn) { slot = t; break; } }
            a = g_tgt_a[i];
        } else { slot = 0; a = fill; }
        float p0 = 0.f, p1 = 0.f;
        #pragma unroll
        for (int k = 0; k < 4; k++) {
            int cc = lane + 32 * k;
            float vv = g_xl2[slot * HC + cc] + sxr[cc] + a * We2[cc];
            vv = lrelu(vv);
            float p = vv * att2[cc];
            if (k < 2) p0 += p; else p1 += p;
        }
        #pragma unroll
        for (int off = 16; off; off >>= 1) {
            p0 += __shfl_down_sync(0xffffffffu, p0, off);
            p1 += __shfl_down_sync(0xffffffffu, p1, off);
        }
        if (lane == 0) {
            float e0 = expf(p0), e1 = expf(p1);
            sal0[i] = e0; sal1[i] = e1;
            sslot[i] = slot;
            atomicAdd(&tsum0, e0); atomicAdd(&tsum1, e1);
        }
    }
    __syncthreads();

    float inv = (c < 64) ? (1.f / tsum0) : (1.f / tsum1);
    float agg = 0.f;
    for (int i = q; i < items; i += 4) {
        float al = ((c < 64) ? sal0[i] : sal1[i]) * inv;
        agg = fmaf(al, g_xl2[sslot[i] * HC + c], agg);
    }
    if (q > 0) sred2[q - 1][c] = agg;
    __syncthreads();
    if (q == 0) sO[c] = agg + sred2[0][c] + sred2[1][c] + sred2[2][c] + b2[c];
    __syncthreads();

    float r = 0.f;
    const float* Wf = Wfc + (q * 32) * HC + c;
    #pragma unroll
    for (int k = 0; k < 32; k++)
        r = fmaf(sO[q * 32 + k], Wf[k * HC], r);
    if (q > 0) sred2[q - 1][c] = r;
    __syncthreads();
    if (q == 0) out[c] = r + sred2[0][c] + sred2[1][c] + sred2[2][c] + bfc[c];
}

// ---------------- launch ----------------
extern "C" void kernel_launch(void* const* d_in, const int* in_sizes, int n_in,
                              void* d_out, int out_size) {
    const float* x    = (const float*)d_in[0];
    const int*   ei   = (const int*)  d_in[1];
    const float* ea   = (const float*)d_in[2];
    const int*   tgtp = (const int*)  d_in[3];
    const float* Wl1  = (const float*)d_in[4];
    const float* bl1  = (const float*)d_in[5];
    const float* Wr1  = (const float*)d_in[6];
    const float* br1  = (const float*)d_in[7];
    const float* We1  = (const float*)d_in[8];
    const float* att1 = (const float*)d_in[9];
    const float* b1   = (const float*)d_in[10];
    const float* Wl2  = (const float*)d_in[11];
    const float* bl2  = (const float*)d_in[12];
    const float* Wr2  = (const float*)d_in[13];
    const float* br2  = (const float*)d_in[14];
    const float* We2  = (const float*)d_in[15];
    const float* att2 = (const float*)d_in[16];
    const float* b2   = (const float*)d_in[17];
    const float* Wfc  = (const float*)d_in[18];
    const float* bfc  = (const float*)d_in[19];
    float* out = (float*)d_out;

    int E = in_sizes[1] / 2;
    const int* src = ei;
    const int* dst = ei + E;

    k_reset<<<8, 256>>>(tgtp);
    k_scan1<<<592, 256>>>(src, dst, ea, tgtp, E);
    k_scan2<<<592, 256>>>(src, dst, ea, x, E);
    k_stats<<<STB, 256>>>(x, Wl1, bl1, Wr1, br1, We1, att1, E);
    k_gemm <<<64, 512>>>(Wl1, bl1, b1, Wl2, bl2, Wr2, br2);
    k_final<<<1, 512>>>(We2, att2, b2, Wfc, bfc, out);
    (void)n_in; (void)out_size;
}